// round 8
// baseline (speedup 1.0000x reference)
#include <cuda_runtime.h>

// Shapes (fixed): B=8, L=256, F=512, U=512.
#define Bn 8
#define Ln 256
#define Fn 512
#define Un 512
#define Mn (Bn*Ln)   // 2048

// Scratch
__device__ __align__(16) float g_Q[Mn * Un];        // [2048][512]
__device__ __align__(16) float g_KT[Bn * Un * Ln];  // [8][512][256]  K+bh, u-major
__device__ __align__(16) float g_A[Bn * Ln * Ln];   // [8][256][256]  normalized weights

__device__ __forceinline__ float tanh_approx(float x) {
    float y;
    asm("tanh.approx.f32 %0, %1;" : "=f"(y) : "f"(x));
    return y;
}

// ---------------------------------------------------------------------------
// Kernel 1: dual SGEMM (round-2 proven version, 49.6 us measured).
// Q = X*Wq and KT = (X*Wk + bh)^T. 64x64 tile, BK=16, 256 threads, 4x4 dual
// microtile, scalar FFMA.
// ---------------------------------------------------------------------------
#define BM 64
#define BN 64
#define BK 16

__global__ __launch_bounds__(256) void proj_kernel(
    const float* __restrict__ X,    // [2048,512]
    const float* __restrict__ Wq,   // [512,512]
    const float* __restrict__ Wk,   // [512,512]
    const float* __restrict__ bh)   // [512]
{
    __shared__ float As[BK][BM];
    __shared__ float B1s[BK][BN];
    __shared__ float B2s[BK][BN];

    const int tid = threadIdx.x;
    const int tx = tid & 15;   // n direction
    const int ty = tid >> 4;   // m direction
    const int m0 = blockIdx.y * BM;
    const int n0 = blockIdx.x * BN;

    float acc1[4][4], acc2[4][4];
#pragma unroll
    for (int i = 0; i < 4; i++)
#pragma unroll
        for (int j = 0; j < 4; j++) { acc1[i][j] = 0.f; acc2[i][j] = 0.f; }

    const int a_row = tid >> 2;
    const int a_k4  = (tid & 3) * 4;
    const int b_k  = tid >> 4;
    const int b_n4 = (tid & 15) * 4;

    for (int k0 = 0; k0 < Fn; k0 += BK) {
        float4 av  = *(const float4*)&X [(m0 + a_row) * Fn + k0 + a_k4];
        float4 bv1 = *(const float4*)&Wq[(k0 + b_k) * Un + n0 + b_n4];
        float4 bv2 = *(const float4*)&Wk[(k0 + b_k) * Un + n0 + b_n4];

        As[a_k4 + 0][a_row] = av.x;
        As[a_k4 + 1][a_row] = av.y;
        As[a_k4 + 2][a_row] = av.z;
        As[a_k4 + 3][a_row] = av.w;
        *(float4*)&B1s[b_k][b_n4] = bv1;
        *(float4*)&B2s[b_k][b_n4] = bv2;
        __syncthreads();

#pragma unroll
        for (int kk = 0; kk < BK; kk++) {
            float4 a4 = *(const float4*)&As [kk][ty * 4];
            float4 c4 = *(const float4*)&B1s[kk][tx * 4];
            float4 d4 = *(const float4*)&B2s[kk][tx * 4];
            float a[4] = {a4.x, a4.y, a4.z, a4.w};
            float c[4] = {c4.x, c4.y, c4.z, c4.w};
            float d[4] = {d4.x, d4.y, d4.z, d4.w};
#pragma unroll
            for (int i = 0; i < 4; i++)
#pragma unroll
                for (int j = 0; j < 4; j++) {
                    acc1[i][j] = fmaf(a[i], c[j], acc1[i][j]);
                    acc2[i][j] = fmaf(a[i], d[j], acc2[i][j]);
                }
        }
        __syncthreads();
    }

#pragma unroll
    for (int i = 0; i < 4; i++) {
        int m = m0 + ty * 4 + i;
        float4 v = make_float4(acc1[i][0], acc1[i][1], acc1[i][2], acc1[i][3]);
        *(float4*)&g_Q[m * Un + n0 + tx * 4] = v;
    }
    {
        const int bidx = m0 >> 8;
        const int q0 = (m0 & 255) + ty * 4;
#pragma unroll
        for (int j = 0; j < 4; j++) {
            int u = n0 + tx * 4 + j;
            float bhv = __ldg(&bh[u]);
            float4 v = make_float4(acc2[0][j] + bhv, acc2[1][j] + bhv,
                                   acc2[2][j] + bhv, acc2[3][j] + bhv);
            *(float4*)&g_KT[(bidx * Un + u) * Ln + q0] = v;
        }
    }
}

// ---------------------------------------------------------------------------
// Kernel 2: additive-attention scores (MUFU-bound). 512 CTAs x 256 threads
// (4 CTAs/SM resident -> single wave; CTA overheads overlap).
// Thread = (us 0..3 of 4 u-splits, qg 0..63 of 4-wide q groups); u-chunk 128.
// 16 tanh per iter behind 1 LDG.128 + 1 LDS.128. Reduce + normalize -> g_A.
// ---------------------------------------------------------------------------
#define PT 4
#define USPLIT 4
#define UCH (Un/USPLIT)   // 128

__global__ __launch_bounds__(256) void attn_kernel(
    const float* __restrict__ Wv)   // [512]
{
    __shared__ float4 QsT[Un];             // [u] -> Q[p0..p0+3][u]   8 KB
    __shared__ float  Wvs[Un];             // 2 KB
    __shared__ float  ep[USPLIT * PT * Ln]; // [us][p][q] = [4][4][256]  16 KB
    __shared__ float  aT[Ln * PT];         // [q][p]  4 KB

    const int tid = threadIdx.x;
    const int b  = blockIdx.x >> 6;
    const int p0 = (blockIdx.x & 63) * PT;

    // Stage Q transposed and Wv
    {
        float* qst = (float*)QsT;
#pragma unroll
        for (int i = tid; i < PT * Un; i += 256) {
            int p = i >> 9;
            int u = i & 511;
            qst[u * 4 + p] = g_Q[(b * Ln + p0 + p) * Un + u];
        }
#pragma unroll
        for (int i = tid; i < Un; i += 256) Wvs[i] = Wv[i];
    }
    __syncthreads();

    const int us = tid >> 6;       // 0..3
    const int qg = tid & 63;       // q-group (4 wide)
    const float4* __restrict__ kt4 = (const float4*)(g_KT + (size_t)b * Un * Ln);

    float4 e0 = make_float4(0.f,0.f,0.f,0.f), e1 = e0, e2 = e0, e3 = e0;
    const int u0 = us * UCH;
#pragma unroll 4
    for (int i = 0; i < UCH; i++) {
        const int u = u0 + i;
        float4 kv = __ldg(&kt4[u * 64 + qg]);
        float4 q4 = QsT[u];
        float  wv = Wvs[u];
        e0.x = fmaf(wv, tanh_approx(q4.x + kv.x), e0.x);
        e0.y = fmaf(wv, tanh_approx(q4.x + kv.y), e0.y);
        e0.z = fmaf(wv, tanh_approx(q4.x + kv.z), e0.z);
        e0.w = fmaf(wv, tanh_approx(q4.x + kv.w), e0.w);
        e1.x = fmaf(wv, tanh_approx(q4.y + kv.x), e1.x);
        e1.y = fmaf(wv, tanh_approx(q4.y + kv.y), e1.y);
        e1.z = fmaf(wv, tanh_approx(q4.y + kv.z), e1.z);
        e1.w = fmaf(wv, tanh_approx(q4.y + kv.w), e1.w);
        e2.x = fmaf(wv, tanh_approx(q4.z + kv.x), e2.x);
        e2.y = fmaf(wv, tanh_approx(q4.z + kv.y), e2.y);
        e2.z = fmaf(wv, tanh_approx(q4.z + kv.z), e2.z);
        e2.w = fmaf(wv, tanh_approx(q4.z + kv.w), e2.w);
        e3.x = fmaf(wv, tanh_approx(q4.w + kv.x), e3.x);
        e3.y = fmaf(wv, tanh_approx(q4.w + kv.y), e3.y);
        e3.z = fmaf(wv, tanh_approx(q4.w + kv.z), e3.z);
        e3.w = fmaf(wv, tanh_approx(q4.w + kv.w), e3.w);
    }
    // ba is a uniform shift of e -> cancels exactly in the exp-normalize.

    {
        float4* ep4 = (float4*)ep;
        ep4[(us * 4 + 0) * 64 + qg] = e0;
        ep4[(us * 4 + 1) * 64 + qg] = e1;
        ep4[(us * 4 + 2) * 64 + qg] = e2;
        ep4[(us * 4 + 3) * 64 + qg] = e3;
    }
    __syncthreads();

    // Reduce 4 u-split partials -> aT[q][p]
#pragma unroll
    for (int idx = tid; idx < PT * Ln; idx += 256) {
        int p = idx >> 8;
        int q = idx & 255;
        float s = ep[(0 * 4 + p) * 256 + q]
                + ep[(1 * 4 + p) * 256 + q]
                + ep[(2 * 4 + p) * 256 + q]
                + ep[(3 * 4 + p) * 256 + q];
        aT[q * 4 + p] = s;
    }
    __syncthreads();

    // Normalize rows in place: warp w handles row p = w (w < 4)
    {
        const int w = tid >> 5, l = tid & 31;
        if (w < PT) {
            float m = -1e30f;
#pragma unroll
            for (int j = 0; j < 8; j++) m = fmaxf(m, aT[(l + j * 32) * 4 + w]);
#pragma unroll
            for (int o = 16; o > 0; o >>= 1)
                m = fmaxf(m, __shfl_xor_sync(0xffffffffu, m, o));
            float ex[8];
            float s = 0.f;
#pragma unroll
            for (int j = 0; j < 8; j++) {
                ex[j] = __expf(aT[(l + j * 32) * 4 + w] - m);
                s += ex[j];
            }
#pragma unroll
            for (int o = 16; o > 0; o >>= 1)
                s += __shfl_xor_sync(0xffffffffu, s, o);
            float inv = 1.f / (s + 1e-7f);
#pragma unroll
            for (int j = 0; j < 8; j++) aT[(l + j * 32) * 4 + w] = ex[j] * inv;
        }
    }
    __syncthreads();

    // Store normalized weights: g_A[b][p0+p][q]  (coalesced over q)
#pragma unroll
    for (int idx = tid; idx < PT * Ln; idx += 256) {
        int p = idx >> 8;
        int q = idx & 255;
        g_A[((size_t)b * Ln + p0 + p) * Ln + q] = aT[q * 4 + p];
    }
}

// ---------------------------------------------------------------------------
// Kernel 3: epilogue GEMM out[p,f] = sum_q a[p][q] * X[b,q,f].
// 256 CTAs (64 p-tiles x 4 f-tiles), 256 threads; 32p x 128f tile, q=256.
// ---------------------------------------------------------------------------
#define OPT 32
#define OFT 128
#define APAD 36

__global__ __launch_bounds__(256) void out_kernel(
    const float* __restrict__ X,    // [8,256,512]
    float* __restrict__ out)        // [8,256,512]
{
    __shared__ float aT[Ln * APAD];   // [q][p_local], 36 KB

    const int tid = threadIdx.x;
    const int ftile = blockIdx.x & 3;
    const int ptile = blockIdx.x >> 2;   // 0..63
    const int b = ptile >> 3;
    const int prow0 = (ptile & 7) * OPT;
    const int f0 = ftile * OFT;

    // Load weights tile into smem (coalesced over q)
    {
        const float* asrc = g_A + ((size_t)b * Ln + prow0) * Ln;
#pragma unroll
        for (int idx = tid; idx < OPT * Ln; idx += 256) {
            int p = idx >> 8;
            int q = idx & 255;
            aT[q * APAD + p] = asrc[p * Ln + q];
        }
    }
    __syncthreads();

    // thread = (py 0..7 -> 4 p rows, lane 0..31 -> 4 f cols)
    const int py = tid >> 5;
    const int lane = tid & 31;
    const float4* __restrict__ xin4 =
        (const float4*)(X + (size_t)b * Ln * Fn) + ftile * 32 + lane;

    float4 o0 = make_float4(0.f,0.f,0.f,0.f), o1 = o0, o2 = o0, o3 = o0;
#pragma unroll 4
    for (int q = 0; q < Ln; q++) {
        float4 x4 = __ldg(&xin4[q * (Fn / 4)]);
        float4 a4 = *(const float4*)&aT[q * APAD + py * 4];  // warp-broadcast
        o0.x = fmaf(a4.x, x4.x, o0.x); o0.y = fmaf(a4.x, x4.y, o0.y);
        o0.z = fmaf(a4.x, x4.z, o0.z); o0.w = fmaf(a4.x, x4.w, o0.w);
        o1.x = fmaf(a4.y, x4.x, o1.x); o1.y = fmaf(a4.y, x4.y, o1.y);
        o1.z = fmaf(a4.y, x4.z, o1.z); o1.w = fmaf(a4.y, x4.w, o1.w);
        o2.x = fmaf(a4.z, x4.x, o2.x); o2.y = fmaf(a4.z, x4.y, o2.y);
        o2.z = fmaf(a4.z, x4.z, o2.z); o2.w = fmaf(a4.z, x4.w, o2.w);
        o3.x = fmaf(a4.w, x4.x, o3.x); o3.y = fmaf(a4.w, x4.y, o3.y);
        o3.z = fmaf(a4.w, x4.z, o3.z); o3.w = fmaf(a4.w, x4.w, o3.w);
    }

    float* obase = out + ((size_t)b * Ln + prow0 + py * 4) * Fn + f0 + lane * 4;
    *(float4*)&obase[0 * Fn] = o0;
    *(float4*)&obase[1 * Fn] = o1;
    *(float4*)&obase[2 * Fn] = o2;
    *(float4*)&obase[3 * Fn] = o3;
}

extern "C" void kernel_launch(void* const* d_in, const int* in_sizes, int n_in,
                              void* d_out, int out_size) {
    const float* X  = (const float*)d_in[0];
    const float* Wq = (const float*)d_in[1];
    const float* Wk = (const float*)d_in[2];
    const float* Wv = (const float*)d_in[3];
    const float* bh = (const float*)d_in[4];
    // d_in[5] = ba: cancels exactly in the exp-normalize; unused.
    float* out = (float*)d_out;

    dim3 gridP(Un / BN, Mn / BM);              // (8, 32) = 256 CTAs
    proj_kernel<<<gridP, 256>>>(X, Wq, Wk, bh);

    attn_kernel<<<Bn * (Ln / PT), 256>>>(Wv);  // 512 CTAs

    out_kernel<<<(Mn / OPT) * (Fn / OFT), 256>>>(X, out);  // 256 CTAs
}

// round 9
// speedup vs baseline: 1.0514x; 1.0514x over previous
#include <cuda_runtime.h>
#include <cstdint>

// Shapes (fixed): B=8, L=256, F=512, U=512.
#define Bn 8
#define Ln 256
#define Fn 512
#define Un 512
#define Mn (Bn*Ln)   // 2048

// Scratch
__device__ __align__(16) float g_Q[Mn * Un];        // [2048][512]
__device__ __align__(16) float g_KT[Bn * Un * Ln];  // [8][512][256]  K+bh, u-major
__device__ __align__(16) float g_A[Bn * Ln * Ln];   // [8][256][256]  normalized weights

__device__ __forceinline__ float tanh_approx(float x) {
    float y;
    asm("tanh.approx.f32 %0, %1;" : "=f"(y) : "f"(x));
    return y;
}

__device__ __forceinline__ uint32_t cvt_tf32(float x) {
    uint32_t r;
    asm("cvt.rna.tf32.f32 %0, %1;" : "=r"(r) : "f"(x));
    return r;
}

#define MMA_TF32(c, A0, A1, A2, A3, B0, B1)                                   \
    asm volatile(                                                             \
        "mma.sync.aligned.m16n8k8.row.col.f32.tf32.tf32.f32 "                 \
        "{%0,%1,%2,%3}, {%4,%5,%6,%7}, {%8,%9}, {%0,%1,%2,%3};"               \
        : "+f"((c)[0]), "+f"((c)[1]), "+f"((c)[2]), "+f"((c)[3])              \
        : "r"(A0), "r"(A1), "r"(A2), "r"(A3), "r"(B0), "r"(B1))

// ---------------------------------------------------------------------------
// Kernel 1: tensor-core projections (tf32 mma.sync, m16n8k8).
// 128 CTAs: bx>>6 selects output (0=Q with Wq, 1=K with Wk), remaining 6 bits
// select one 128x128 tile of the 2048x512 result. 8 warps as 2m x 4n grid,
// warp tile 64x32 = 4 m16-tiles x 4 n8-tiles. Double-buffered reg fragments.
// Q stored row-major to g_Q; K transposed through smem (+bh) into g_KT.
// ---------------------------------------------------------------------------
__global__ __launch_bounds__(256) void proj_tc_kernel(
    const float* __restrict__ X,    // [2048,512]
    const float* __restrict__ Wq,   // [512,512]
    const float* __restrict__ Wk,   // [512,512]
    const float* __restrict__ bh)   // [512]
{
    __shared__ float kbuf[128][65];  // transpose staging (33 KB, conflict-free)

    const int bx  = blockIdx.x;
    const int isK = bx >> 6;
    const int m0  = ((bx >> 2) & 15) * 128;
    const int n0  = (bx & 3) * 128;
    const float* __restrict__ W = isK ? Wk : Wq;

    const int wid  = threadIdx.x >> 5;
    const int lane = threadIdx.x & 31;
    const int mw = wid >> 2;        // 0..1
    const int nw = wid & 3;         // 0..3
    const int gid = lane >> 2;      // 0..7
    const int tig = lane & 3;       // 0..3

    const float* __restrict__ Ab = X + (size_t)(m0 + mw * 64) * Fn;
    const float* __restrict__ Bb = W + n0 + nw * 32;

    float acc[4][4][4];
#pragma unroll
    for (int i = 0; i < 4; i++)
#pragma unroll
        for (int j = 0; j < 4; j++)
#pragma unroll
            for (int r = 0; r < 4; r++) acc[i][j][r] = 0.f;

    uint32_t a[2][4][4], b[2][4][2];

#define LOADA(S, K0)                                                          \
    do {                                                                      \
        _Pragma("unroll")                                                     \
        for (int mt = 0; mt < 4; mt++) {                                      \
            const float* p = Ab + (mt * 16 + gid) * Fn + (K0) + tig;          \
            a[S][mt][0] = cvt_tf32(p[0]);                                     \
            a[S][mt][2] = cvt_tf32(p[4]);                                     \
            a[S][mt][1] = cvt_tf32(p[8 * Fn]);                                \
            a[S][mt][3] = cvt_tf32(p[8 * Fn + 4]);                            \
        }                                                                     \
    } while (0)
#define LOADB(S, K0)                                                          \
    do {                                                                      \
        _Pragma("unroll")                                                     \
        for (int nt = 0; nt < 4; nt++) {                                      \
            const float* p = Bb + ((K0) + tig) * Un + nt * 8 + gid;           \
            b[S][nt][0] = cvt_tf32(p[0]);                                     \
            b[S][nt][1] = cvt_tf32(p[4 * Un]);                                \
        }                                                                     \
    } while (0)
#define MMA_ALL(S)                                                            \
    do {                                                                      \
        _Pragma("unroll")                                                     \
        for (int mt = 0; mt < 4; mt++)                                        \
            _Pragma("unroll")                                                 \
            for (int nt = 0; nt < 4; nt++)                                    \
                MMA_TF32(acc[mt][nt], a[S][mt][0], a[S][mt][1],               \
                         a[S][mt][2], a[S][mt][3], b[S][nt][0], b[S][nt][1]); \
    } while (0)

    LOADA(0, 0); LOADB(0, 0);
    for (int ks = 0; ks < 64; ks += 2) {
        LOADA(1, (ks + 1) * 8);
        LOADB(1, (ks + 1) * 8);
        MMA_ALL(0);
        if (ks + 2 < 64) {
            LOADA(0, (ks + 2) * 8);
            LOADB(0, (ks + 2) * 8);
        }
        MMA_ALL(1);
    }

    if (!isK) {
        // Q epilogue: direct row-major float2 stores
#pragma unroll
        for (int mt = 0; mt < 4; mt++) {
#pragma unroll
            for (int nt = 0; nt < 4; nt++) {
                const int row = m0 + mw * 64 + mt * 16 + gid;
                const int col = n0 + nw * 32 + nt * 8 + 2 * tig;
                float2 lo = make_float2(acc[mt][nt][0], acc[mt][nt][1]);
                float2 hi = make_float2(acc[mt][nt][2], acc[mt][nt][3]);
                *(float2*)&g_Q[(size_t)row * Un + col]       = lo;
                *(float2*)&g_Q[(size_t)(row + 8) * Un + col] = hi;
            }
        }
    } else {
        // K epilogue: transpose 128x128 tile via smem in two 64-col passes,
        // add bh, store KT[b][u][q].
        const int bidx = m0 >> 8;          // batch (128-tile never spans 256)
        const int qi0  = m0 & 255;         // 0 or 128
#pragma unroll
        for (int pass = 0; pass < 2; pass++) {
            __syncthreads();
            if ((nw >> 1) == pass) {
#pragma unroll
                for (int mt = 0; mt < 4; mt++) {
#pragma unroll
                    for (int nt = 0; nt < 4; nt++) {
                        const int row = mw * 64 + mt * 16 + gid;
                        const int cl  = (nw & 1) * 32 + nt * 8 + 2 * tig;
                        kbuf[row][cl]         = acc[mt][nt][0];
                        kbuf[row][cl + 1]     = acc[mt][nt][1];
                        kbuf[row + 8][cl]     = acc[mt][nt][2];
                        kbuf[row + 8][cl + 1] = acc[mt][nt][3];
                    }
                }
            }
            __syncthreads();
#pragma unroll
            for (int i = threadIdx.x; i < 64 * 128; i += 256) {
                const int ul = i >> 7;
                const int q  = i & 127;
                const int u  = n0 + pass * 64 + ul;
                g_KT[((size_t)bidx * Un + u) * Ln + qi0 + q] =
                    kbuf[q][ul] + __ldg(&bh[u]);
            }
        }
    }
#undef LOADA
#undef LOADB
#undef MMA_ALL
}

// ---------------------------------------------------------------------------
// Kernel 2: additive-attention scores (MUFU-bound). 512 CTAs x 256 threads.
// Thread = (us 0..3 of 4 u-splits, qg 0..63 of 4-wide q groups); u-chunk 128.
// 16 tanh per iter behind 1 LDG.128 + 1 LDS.128. Reduce + normalize -> g_A.
// ---------------------------------------------------------------------------
#define PT 4
#define USPLIT 4
#define UCH (Un/USPLIT)   // 128

__global__ __launch_bounds__(256) void attn_kernel(
    const float* __restrict__ Wv)   // [512]
{
    __shared__ float4 QsT[Un];             // [u] -> Q[p0..p0+3][u]   8 KB
    __shared__ float  Wvs[Un];             // 2 KB
    __shared__ float  ep[USPLIT * PT * Ln]; // [us][p][q] = [4][4][256]  16 KB
    __shared__ float  aT[Ln * PT];         // [q][p]  4 KB

    const int tid = threadIdx.x;
    const int b  = blockIdx.x >> 6;
    const int p0 = (blockIdx.x & 63) * PT;

    // Stage Q transposed and Wv
    {
        float* qst = (float*)QsT;
#pragma unroll
        for (int i = tid; i < PT * Un; i += 256) {
            int p = i >> 9;
            int u = i & 511;
            qst[u * 4 + p] = g_Q[(b * Ln + p0 + p) * Un + u];
        }
#pragma unroll
        for (int i = tid; i < Un; i += 256) Wvs[i] = Wv[i];
    }
    __syncthreads();

    const int us = tid >> 6;       // 0..3
    const int qg = tid & 63;       // q-group (4 wide)
    const float4* __restrict__ kt4 = (const float4*)(g_KT + (size_t)b * Un * Ln);

    float4 e0 = make_float4(0.f,0.f,0.f,0.f), e1 = e0, e2 = e0, e3 = e0;
    const int u0 = us * UCH;
#pragma unroll 4
    for (int i = 0; i < UCH; i++) {
        const int u = u0 + i;
        float4 kv = __ldg(&kt4[u * 64 + qg]);
        float4 q4 = QsT[u];
        float  wv = Wvs[u];
        e0.x = fmaf(wv, tanh_approx(q4.x + kv.x), e0.x);
        e0.y = fmaf(wv, tanh_approx(q4.x + kv.y), e0.y);
        e0.z = fmaf(wv, tanh_approx(q4.x + kv.z), e0.z);
        e0.w = fmaf(wv, tanh_approx(q4.x + kv.w), e0.w);
        e1.x = fmaf(wv, tanh_approx(q4.y + kv.x), e1.x);
        e1.y = fmaf(wv, tanh_approx(q4.y + kv.y), e1.y);
        e1.z = fmaf(wv, tanh_approx(q4.y + kv.z), e1.z);
        e1.w = fmaf(wv, tanh_approx(q4.y + kv.w), e1.w);
        e2.x = fmaf(wv, tanh_approx(q4.z + kv.x), e2.x);
        e2.y = fmaf(wv, tanh_approx(q4.z + kv.y), e2.y);
        e2.z = fmaf(wv, tanh_approx(q4.z + kv.z), e2.z);
        e2.w = fmaf(wv, tanh_approx(q4.z + kv.w), e2.w);
        e3.x = fmaf(wv, tanh_approx(q4.w + kv.x), e3.x);
        e3.y = fmaf(wv, tanh_approx(q4.w + kv.y), e3.y);
        e3.z = fmaf(wv, tanh_approx(q4.w + kv.z), e3.z);
        e3.w = fmaf(wv, tanh_approx(q4.w + kv.w), e3.w);
    }
    // ba is a uniform shift of e -> cancels exactly in the exp-normalize.

    {
        float4* ep4 = (float4*)ep;
        ep4[(us * 4 + 0) * 64 + qg] = e0;
        ep4[(us * 4 + 1) * 64 + qg] = e1;
        ep4[(us * 4 + 2) * 64 + qg] = e2;
        ep4[(us * 4 + 3) * 64 + qg] = e3;
    }
    __syncthreads();

    // Reduce 4 u-split partials -> aT[q][p]
#pragma unroll
    for (int idx = tid; idx < PT * Ln; idx += 256) {
        int p = idx >> 8;
        int q = idx & 255;
        float s = ep[(0 * 4 + p) * 256 + q]
                + ep[(1 * 4 + p) * 256 + q]
                + ep[(2 * 4 + p) * 256 + q]
                + ep[(3 * 4 + p) * 256 + q];
        aT[q * 4 + p] = s;
    }
    __syncthreads();

    // Normalize rows in place: warp w handles row p = w (w < 4)
    {
        const int w = tid >> 5, l = tid & 31;
        if (w < PT) {
            float m = -1e30f;
#pragma unroll
            for (int j = 0; j < 8; j++) m = fmaxf(m, aT[(l + j * 32) * 4 + w]);
#pragma unroll
            for (int o = 16; o > 0; o >>= 1)
                m = fmaxf(m, __shfl_xor_sync(0xffffffffu, m, o));
            float ex[8];
            float s = 0.f;
#pragma unroll
            for (int j = 0; j < 8; j++) {
                ex[j] = __expf(aT[(l + j * 32) * 4 + w] - m);
                s += ex[j];
            }
#pragma unroll
            for (int o = 16; o > 0; o >>= 1)
                s += __shfl_xor_sync(0xffffffffu, s, o);
            float inv = 1.f / (s + 1e-7f);
#pragma unroll
            for (int j = 0; j < 8; j++) aT[(l + j * 32) * 4 + w] = ex[j] * inv;
        }
    }
    __syncthreads();

    // Store normalized weights: g_A[b][p0+p][q]  (coalesced over q)
#pragma unroll
    for (int idx = tid; idx < PT * Ln; idx += 256) {
        int p = idx >> 8;
        int q = idx & 255;
        g_A[((size_t)b * Ln + p0 + p) * Ln + q] = aT[q * 4 + p];
    }
}

// ---------------------------------------------------------------------------
// Kernel 3: epilogue GEMM out[p,f] = sum_q a[p][q] * X[b,q,f].
// 256 CTAs (64 p-tiles x 4 f-tiles), 256 threads; 32p x 128f tile, q=256.
// ---------------------------------------------------------------------------
#define OPT 32
#define OFT 128
#define APAD 36

__global__ __launch_bounds__(256) void out_kernel(
    const float* __restrict__ X,    // [8,256,512]
    float* __restrict__ out)        // [8,256,512]
{
    __shared__ float aT[Ln * APAD];   // [q][p_local], 36 KB

    const int tid = threadIdx.x;
    const int ftile = blockIdx.x & 3;
    const int ptile = blockIdx.x >> 2;   // 0..63
    const int b = ptile >> 3;
    const int prow0 = (ptile & 7) * OPT;
    const int f0 = ftile * OFT;

    // Load weights tile into smem (coalesced over q)
    {
        const float* asrc = g_A + ((size_t)b * Ln + prow0) * Ln;
#pragma unroll
        for (int idx = tid; idx < OPT * Ln; idx += 256) {
            int p = idx >> 8;
            int q = idx & 255;
            aT[q * APAD + p] = asrc[p * Ln + q];
        }
    }
    __syncthreads();

    // thread = (py 0..7 -> 4 p rows, lane 0..31 -> 4 f cols)
    const int py = tid >> 5;
    const int lane = tid & 31;
    const float4* __restrict__ xin4 =
        (const float4*)(X + (size_t)b * Ln * Fn) + ftile * 32 + lane;

    float4 o0 = make_float4(0.f,0.f,0.f,0.f), o1 = o0, o2 = o0, o3 = o0;
#pragma unroll 4
    for (int q = 0; q < Ln; q++) {
        float4 x4 = __ldg(&xin4[q * (Fn / 4)]);
        float4 a4 = *(const float4*)&aT[q * APAD + py * 4];  // warp-broadcast
        o0.x = fmaf(a4.x, x4.x, o0.x); o0.y = fmaf(a4.x, x4.y, o0.y);
        o0.z = fmaf(a4.x, x4.z, o0.z); o0.w = fmaf(a4.x, x4.w, o0.w);
        o1.x = fmaf(a4.y, x4.x, o1.x); o1.y = fmaf(a4.y, x4.y, o1.y);
        o1.z = fmaf(a4.y, x4.z, o1.z); o1.w = fmaf(a4.y, x4.w, o1.w);
        o2.x = fmaf(a4.z, x4.x, o2.x); o2.y = fmaf(a4.z, x4.y, o2.y);
        o2.z = fmaf(a4.z, x4.z, o2.z); o2.w = fmaf(a4.z, x4.w, o2.w);
        o3.x = fmaf(a4.w, x4.x, o3.x); o3.y = fmaf(a4.w, x4.y, o3.y);
        o3.z = fmaf(a4.w, x4.z, o3.z); o3.w = fmaf(a4.w, x4.w, o3.w);
    }

    float* obase = out + ((size_t)b * Ln + prow0 + py * 4) * Fn + f0 + lane * 4;
    *(float4*)&obase[0 * Fn] = o0;
    *(float4*)&obase[1 * Fn] = o1;
    *(float4*)&obase[2 * Fn] = o2;
    *(float4*)&obase[3 * Fn] = o3;
}

extern "C" void kernel_launch(void* const* d_in, const int* in_sizes, int n_in,
                              void* d_out, int out_size) {
    const float* X  = (const float*)d_in[0];
    const float* Wq = (const float*)d_in[1];
    const float* Wk = (const float*)d_in[2];
    const float* Wv = (const float*)d_in[3];
    const float* bh = (const float*)d_in[4];
    // d_in[5] = ba: cancels exactly in the exp-normalize; unused.
    float* out = (float*)d_out;

    proj_tc_kernel<<<128, 256>>>(X, Wq, Wk, bh);     // 128 CTAs, single wave

    attn_kernel<<<Bn * (Ln / PT), 256>>>(Wv);        // 512 CTAs

    out_kernel<<<(Mn / OPT) * (Fn / OFT), 256>>>(X, out);  // 256 CTAs
}

// round 10
// speedup vs baseline: 1.1879x; 1.1298x over previous
#include <cuda_runtime.h>
#include <cstdint>

// Shapes (fixed): B=8, L=256, F=512, U=512.
#define Bn 8
#define Ln 256
#define Fn 512
#define Un 512
#define Mn (Bn*Ln)   // 2048

// Scratch
__device__ __align__(16) float g_Q[Mn * Un];        // [2048][512]
__device__ __align__(16) float g_KT[Bn * Un * Ln];  // [8][512][256]  K+bh, u-major

__device__ __forceinline__ float tanh_approx(float x) {
    float y;
    asm("tanh.approx.f32 %0, %1;" : "=f"(y) : "f"(x));
    return y;
}

__device__ __forceinline__ uint32_t cvt_tf32(float x) {
    uint32_t r;
    asm("cvt.rna.tf32.f32 %0, %1;" : "=r"(r) : "f"(x));
    return r;
}

#define MMA_TF32(c, A0, A1, A2, A3, B0, B1)                                   \
    asm volatile(                                                             \
        "mma.sync.aligned.m16n8k8.row.col.f32.tf32.tf32.f32 "                 \
        "{%0,%1,%2,%3}, {%4,%5,%6,%7}, {%8,%9}, {%0,%1,%2,%3};"               \
        : "+f"((c)[0]), "+f"((c)[1]), "+f"((c)[2]), "+f"((c)[3])              \
        : "r"(A0), "r"(A1), "r"(A2), "r"(A3), "r"(B0), "r"(B1))

// ---------------------------------------------------------------------------
// Kernel 1: tensor-core projections, smem-staged.
// 128 CTAs: bx>>6 selects output (0=Q/Wq, 1=K/Wk); 128x128 tile per CTA.
// Double-buffered smem: As[2][128][20] (m-major, pad 20 -> conflict-free
// fragment LDS), Bs[2][16][136] (k-major, pad 136 -> conflict-free).
// 8 warps as 2m x 4n; warp tile 64x32 = 4x4 m16n8k8 tf32 MMAs per k-step.
// ---------------------------------------------------------------------------
#define APITCH 20
#define BPITCH 136
#define A_FLOATS (2 * 128 * APITCH)   // 5120
#define B_FLOATS (2 * 16 * BPITCH)    // 4352

__global__ __launch_bounds__(256) void proj_tc_kernel(
    const float* __restrict__ X,    // [2048,512]
    const float* __restrict__ Wq,   // [512,512]
    const float* __restrict__ Wk,   // [512,512]
    const float* __restrict__ bh)   // [512]
{
    __shared__ __align__(16) float pool[A_FLOATS + B_FLOATS];  // 37.9 KB
    typedef float ATile[128][APITCH];
    typedef float BTile[16][BPITCH];
    ATile* As = (ATile*)pool;                 // As[0], As[1]
    BTile* Bs = (BTile*)(pool + A_FLOATS);    // Bs[0], Bs[1]
    typedef float KRow[65];
    KRow* kbuf = (KRow*)pool;                 // epilogue alias: 128*65 floats

    const int bx  = blockIdx.x;
    const int isK = bx >> 6;
    const int m0  = ((bx >> 2) & 15) * 128;
    const int n0  = (bx & 3) * 128;
    const float* __restrict__ W = isK ? Wk : Wq;

    const int tid  = threadIdx.x;
    const int wid  = tid >> 5;
    const int lane = tid & 31;
    const int mw = wid >> 2;        // 0..1
    const int nw = wid & 3;         // 0..3
    const int gid = lane >> 2;      // 0..7
    const int tig = lane & 3;       // 0..3

    // loader indices
    const int ma  = tid >> 2;          // 0..63 (rows ma, ma+64)
    const int k4a = (tid & 3) * 4;     // 0,4,8,12
    const int kb  = tid >> 5;          // 0..7 (rows kb, kb+8)
    const int n4b = (tid & 31) * 4;

    float acc[4][4][4];
#pragma unroll
    for (int i = 0; i < 4; i++)
#pragma unroll
        for (int j = 0; j < 4; j++)
#pragma unroll
            for (int r = 0; r < 4; r++) acc[i][j][r] = 0.f;

    float4 av0, av1, bv0, bv1;
#define PLOAD(K0)                                                             \
    do {                                                                      \
        av0 = *(const float4*)&X[(size_t)(m0 + ma) * Fn + (K0) + k4a];        \
        av1 = *(const float4*)&X[(size_t)(m0 + ma + 64) * Fn + (K0) + k4a];   \
        bv0 = *(const float4*)&W[(size_t)((K0) + kb) * Un + n0 + n4b];        \
        bv1 = *(const float4*)&W[(size_t)((K0) + kb + 8) * Un + n0 + n4b];    \
    } while (0)
#define PSTORE(S)                                                             \
    do {                                                                      \
        *(float4*)&As[S][ma][k4a]      = av0;                                 \
        *(float4*)&As[S][ma + 64][k4a] = av1;                                 \
        *(float4*)&Bs[S][kb][n4b]      = bv0;                                 \
        *(float4*)&Bs[S][kb + 8][n4b]  = bv1;                                 \
    } while (0)

    PLOAD(0);
    PSTORE(0);
    __syncthreads();

    for (int c = 0; c < 32; c++) {
        const int s = c & 1;
        if (c + 1 < 32) PLOAD((c + 1) * 16);
#pragma unroll
        for (int kk = 0; kk < 16; kk += 8) {
            uint32_t a[4][4], b[4][2];
#pragma unroll
            for (int mt = 0; mt < 4; mt++) {
                const int row = mw * 64 + mt * 16 + gid;
                a[mt][0] = cvt_tf32(As[s][row][kk + tig]);
                a[mt][1] = cvt_tf32(As[s][row + 8][kk + tig]);
                a[mt][2] = cvt_tf32(As[s][row][kk + tig + 4]);
                a[mt][3] = cvt_tf32(As[s][row + 8][kk + tig + 4]);
            }
#pragma unroll
            for (int nt = 0; nt < 4; nt++) {
                const int col = nw * 32 + nt * 8 + gid;
                b[nt][0] = cvt_tf32(Bs[s][kk + tig][col]);
                b[nt][1] = cvt_tf32(Bs[s][kk + tig + 4][col]);
            }
#pragma unroll
            for (int mt = 0; mt < 4; mt++)
#pragma unroll
                for (int nt = 0; nt < 4; nt++)
                    MMA_TF32(acc[mt][nt], a[mt][0], a[mt][1], a[mt][2],
                             a[mt][3], b[nt][0], b[nt][1]);
        }
        if (c + 1 < 32) {
            PSTORE((c + 1) & 1);
            __syncthreads();
        }
    }

    if (!isK) {
        // Q epilogue: direct row-major float2 stores
#pragma unroll
        for (int mt = 0; mt < 4; mt++) {
#pragma unroll
            for (int nt = 0; nt < 4; nt++) {
                const int row = m0 + mw * 64 + mt * 16 + gid;
                const int col = n0 + nw * 32 + nt * 8 + 2 * tig;
                float2 lo = make_float2(acc[mt][nt][0], acc[mt][nt][1]);
                float2 hi = make_float2(acc[mt][nt][2], acc[mt][nt][3]);
                *(float2*)&g_Q[(size_t)row * Un + col]       = lo;
                *(float2*)&g_Q[(size_t)(row + 8) * Un + col] = hi;
            }
        }
    } else {
        // K epilogue: transpose 128x128 tile via smem (aliases pool), +bh,
        // store KT[b][u][q]. Two 64-col passes.
        const int bidx = m0 >> 8;
        const int qi0  = m0 & 255;
#pragma unroll
        for (int pass = 0; pass < 2; pass++) {
            __syncthreads();
            if ((nw >> 1) == pass) {
#pragma unroll
                for (int mt = 0; mt < 4; mt++) {
#pragma unroll
                    for (int nt = 0; nt < 4; nt++) {
                        const int row = mw * 64 + mt * 16 + gid;
                        const int cl  = (nw & 1) * 32 + nt * 8 + 2 * tig;
                        kbuf[row][cl]         = acc[mt][nt][0];
                        kbuf[row][cl + 1]     = acc[mt][nt][1];
                        kbuf[row + 8][cl]     = acc[mt][nt][2];
                        kbuf[row + 8][cl + 1] = acc[mt][nt][3];
                    }
                }
            }
            __syncthreads();
#pragma unroll
            for (int i = tid; i < 64 * 128; i += 256) {
                const int ul = i >> 7;
                const int q  = i & 127;
                const int u  = n0 + pass * 64 + ul;
                g_KT[((size_t)bidx * Un + u) * Ln + qi0 + q] =
                    kbuf[q][ul] + __ldg(&bh[u]);
            }
        }
    }
#undef PLOAD
#undef PSTORE
}

// ---------------------------------------------------------------------------
// Kernel 2: fused attention (scores + normalize + output GEMM).
// 256 CTAs x 256 threads; CTA = 8 query rows (PT=8) of one batch.
// e-loop: thread = (pg 0..3 -> 2 p, qg 0..63 -> 4 q), full u=512 in-thread
// (no u-split, no partial-reduce smem). 8 tanh/iter behind 1 LDG.128 +
// broadcast LDS. Then per-warp row normalize, smem transpose, fused epilogue.
// ---------------------------------------------------------------------------
#define PT 8

__global__ __launch_bounds__(256) void attn_kernel(
    const float* __restrict__ X,    // [8,256,512]
    const float* __restrict__ Wv,   // [512]
    float* __restrict__ out)        // [8,256,512]
{
    __shared__ float QsT[Un][PT];   // [u][p]  16 KB
    __shared__ float Wvs[Un];       //          2 KB
    __shared__ float aP[PT][Ln];    // [p][q]   8 KB
    __shared__ float aQ[Ln][PT];    // [q][p]   8 KB   (34 KB total)

    const int tid = threadIdx.x;
    const int b  = blockIdx.x >> 5;
    const int p0 = (blockIdx.x & 31) * PT;

    // Stage Q transposed and Wv
#pragma unroll
    for (int i = tid; i < PT * Un; i += 256) {
        int p = i >> 9;          // 0..7
        int u = i & 511;
        QsT[u][p] = g_Q[((size_t)b * Ln + p0 + p) * Un + u];
    }
    Wvs[tid]       = Wv[tid];
    Wvs[tid + 256] = Wv[tid + 256];
    __syncthreads();

    // ---- e-loop ----
    const int pg = tid >> 6;       // 0..3 -> p pair {2pg, 2pg+1}
    const int qg = tid & 63;       // 4-wide q group
    const float4* __restrict__ kt4 = (const float4*)(g_KT + (size_t)b * Un * Ln);

    float4 e0 = make_float4(0.f, 0.f, 0.f, 0.f), e1 = e0;
#pragma unroll 4
    for (int u = 0; u < Un; u++) {
        float4 kv = __ldg(&kt4[u * 64 + qg]);
        float2 qp = *(const float2*)&QsT[u][pg * 2];
        float  wv = Wvs[u];
        e0.x = fmaf(wv, tanh_approx(qp.x + kv.x), e0.x);
        e0.y = fmaf(wv, tanh_approx(qp.x + kv.y), e0.y);
        e0.z = fmaf(wv, tanh_approx(qp.x + kv.z), e0.z);
        e0.w = fmaf(wv, tanh_approx(qp.x + kv.w), e0.w);
        e1.x = fmaf(wv, tanh_approx(qp.y + kv.x), e1.x);
        e1.y = fmaf(wv, tanh_approx(qp.y + kv.y), e1.y);
        e1.z = fmaf(wv, tanh_approx(qp.y + kv.z), e1.z);
        e1.w = fmaf(wv, tanh_approx(qp.y + kv.w), e1.w);
    }
    // ba is a uniform shift of e -> cancels exactly in the exp-normalize.

    aP[pg * 2 + 0][qg * 4 + 0] = e0.x;
    aP[pg * 2 + 0][qg * 4 + 1] = e0.y;
    aP[pg * 2 + 0][qg * 4 + 2] = e0.z;
    aP[pg * 2 + 0][qg * 4 + 3] = e0.w;
    aP[pg * 2 + 1][qg * 4 + 0] = e1.x;
    aP[pg * 2 + 1][qg * 4 + 1] = e1.y;
    aP[pg * 2 + 1][qg * 4 + 2] = e1.z;
    aP[pg * 2 + 1][qg * 4 + 3] = e1.w;
    __syncthreads();

    // ---- normalize: warp w handles row p = w (8 warps, 8 rows) ----
    {
        const int w = tid >> 5, l = tid & 31;
        float v[8];
        float m = -1e30f;
#pragma unroll
        for (int j = 0; j < 8; j++) {
            v[j] = aP[w][l + j * 32];
            m = fmaxf(m, v[j]);
        }
#pragma unroll
        for (int o = 16; o > 0; o >>= 1)
            m = fmaxf(m, __shfl_xor_sync(0xffffffffu, m, o));
        float s = 0.f;
#pragma unroll
        for (int j = 0; j < 8; j++) {
            v[j] = __expf(v[j] - m);
            s += v[j];
        }
#pragma unroll
        for (int o = 16; o > 0; o >>= 1)
            s += __shfl_xor_sync(0xffffffffu, s, o);
        float inv = 1.f / (s + 1e-7f);
#pragma unroll
        for (int j = 0; j < 8; j++) aP[w][l + j * 32] = v[j] * inv;
    }
    __syncthreads();

    // ---- transpose aP[p][q] -> aQ[q][p] (one-shot, cheap) ----
#pragma unroll
    for (int i = tid; i < PT * Ln; i += 256) {
        int p = i >> 8;
        int q = i & 255;
        aQ[q][p] = aP[p][q];
    }
    __syncthreads();

    // ---- fused epilogue: out[p,f] = sum_q a[p][q] * X[b,q,f] ----
    float o0[PT], o1[PT];
#pragma unroll
    for (int p = 0; p < PT; p++) { o0[p] = 0.f; o1[p] = 0.f; }

    const float* __restrict__ xin = X + (size_t)b * Ln * Fn;
#pragma unroll 2
    for (int q = 0; q < Ln; q++) {
        float x0 = __ldg(&xin[q * Fn + tid]);
        float x1 = __ldg(&xin[q * Fn + tid + 256]);
        float4 aa = *(const float4*)&aQ[q][0];   // warp-uniform broadcast
        float4 ab = *(const float4*)&aQ[q][4];
        o0[0] = fmaf(aa.x, x0, o0[0]); o1[0] = fmaf(aa.x, x1, o1[0]);
        o0[1] = fmaf(aa.y, x0, o0[1]); o1[1] = fmaf(aa.y, x1, o1[1]);
        o0[2] = fmaf(aa.z, x0, o0[2]); o1[2] = fmaf(aa.z, x1, o1[2]);
        o0[3] = fmaf(aa.w, x0, o0[3]); o1[3] = fmaf(aa.w, x1, o1[3]);
        o0[4] = fmaf(ab.x, x0, o0[4]); o1[4] = fmaf(ab.x, x1, o1[4]);
        o0[5] = fmaf(ab.y, x0, o0[5]); o1[5] = fmaf(ab.y, x1, o1[5]);
        o0[6] = fmaf(ab.z, x0, o0[6]); o1[6] = fmaf(ab.z, x1, o1[6]);
        o0[7] = fmaf(ab.w, x0, o0[7]); o1[7] = fmaf(ab.w, x1, o1[7]);
    }
#pragma unroll
    for (int p = 0; p < PT; p++) {
        out[((size_t)b * Ln + p0 + p) * Fn + tid]       = o0[p];
        out[((size_t)b * Ln + p0 + p) * Fn + tid + 256] = o1[p];
    }
}

extern "C" void kernel_launch(void* const* d_in, const int* in_sizes, int n_in,
                              void* d_out, int out_size) {
    const float* X  = (const float*)d_in[0];
    const float* Wq = (const float*)d_in[1];
    const float* Wk = (const float*)d_in[2];
    const float* Wv = (const float*)d_in[3];
    const float* bh = (const float*)d_in[4];
    // d_in[5] = ba: cancels exactly in the exp-normalize; unused.
    float* out = (float*)d_out;

    proj_tc_kernel<<<128, 256>>>(X, Wq, Wk, bh);   // 128 CTAs, single wave

    attn_kernel<<<Bn * (Ln / PT), 256>>>(X, Wv, out);  // 256 CTAs
}

// round 11
// speedup vs baseline: 1.2687x; 1.0680x over previous
#include <cuda_runtime.h>
#include <cstdint>

// Shapes (fixed): B=8, L=256, F=512, U=512.
#define Bn 8
#define Ln 256
#define Fn 512
#define Un 512
#define Mn (Bn*Ln)   // 2048

// Scratch
__device__ __align__(16) float g_Q[Mn * Un];        // [2048][512]
__device__ __align__(16) float g_KT[Bn * Un * Ln];  // [8][512][256]  K+bh, u-major

__device__ __forceinline__ float tanh_approx(float x) {
    float y;
    asm("tanh.approx.f32 %0, %1;" : "=f"(y) : "f"(x));
    return y;
}

__device__ __forceinline__ uint32_t cvt_tf32(float x) {
    uint32_t r;
    asm("cvt.rna.tf32.f32 %0, %1;" : "=r"(r) : "f"(x));
    return r;
}

#define MMA_TF32(c, A0, A1, A2, A3, B0, B1)                                   \
    asm volatile(                                                             \
        "mma.sync.aligned.m16n8k8.row.col.f32.tf32.tf32.f32 "                 \
        "{%0,%1,%2,%3}, {%4,%5,%6,%7}, {%8,%9}, {%0,%1,%2,%3};"               \
        : "+f"((c)[0]), "+f"((c)[1]), "+f"((c)[2]), "+f"((c)[3])              \
        : "r"(A0), "r"(A1), "r"(A2), "r"(A3), "r"(B0), "r"(B1))

// ---------------------------------------------------------------------------
// Kernel 1: tensor-core projections, smem-staged (validated round 10, ~20us).
// 128 CTAs: bx>>6 selects output (0=Q/Wq, 1=K/Wk); 128x128 tile per CTA.
// Double-buffered smem As[2][128][20] / Bs[2][16][136], conflict-free.
// 8 warps as 2m x 4n; warp tile 64x32 = 4x4 m16n8k8 tf32 MMAs per k-step.
// ---------------------------------------------------------------------------
#define APITCH 20
#define BPITCH 136
#define A_FLOATS (2 * 128 * APITCH)   // 5120
#define B_FLOATS (2 * 16 * BPITCH)    // 4352

__global__ __launch_bounds__(256) void proj_tc_kernel(
    const float* __restrict__ X,    // [2048,512]
    const float* __restrict__ Wq,   // [512,512]
    const float* __restrict__ Wk,   // [512,512]
    const float* __restrict__ bh)   // [512]
{
    __shared__ __align__(16) float pool[A_FLOATS + B_FLOATS];  // 37.9 KB
    typedef float ATile[128][APITCH];
    typedef float BTile[16][BPITCH];
    ATile* As = (ATile*)pool;
    BTile* Bs = (BTile*)(pool + A_FLOATS);
    typedef float KRow[65];
    KRow* kbuf = (KRow*)pool;   // epilogue alias

    const int bx  = blockIdx.x;
    const int isK = bx >> 6;
    const int m0  = ((bx >> 2) & 15) * 128;
    const int n0  = (bx & 3) * 128;
    const float* __restrict__ W = isK ? Wk : Wq;

    const int tid  = threadIdx.x;
    const int wid  = tid >> 5;
    const int lane = tid & 31;
    const int mw = wid >> 2;
    const int nw = wid & 3;
    const int gid = lane >> 2;
    const int tig = lane & 3;

    const int ma  = tid >> 2;
    const int k4a = (tid & 3) * 4;
    const int kb  = tid >> 5;
    const int n4b = (tid & 31) * 4;

    float acc[4][4][4];
#pragma unroll
    for (int i = 0; i < 4; i++)
#pragma unroll
        for (int j = 0; j < 4; j++)
#pragma unroll
            for (int r = 0; r < 4; r++) acc[i][j][r] = 0.f;

    float4 av0, av1, bv0, bv1;
#define PLOAD(K0)                                                             \
    do {                                                                      \
        av0 = *(const float4*)&X[(size_t)(m0 + ma) * Fn + (K0) + k4a];        \
        av1 = *(const float4*)&X[(size_t)(m0 + ma + 64) * Fn + (K0) + k4a];   \
        bv0 = *(const float4*)&W[(size_t)((K0) + kb) * Un + n0 + n4b];        \
        bv1 = *(const float4*)&W[(size_t)((K0) + kb + 8) * Un + n0 + n4b];    \
    } while (0)
#define PSTORE(S)                                                             \
    do {                                                                      \
        *(float4*)&As[S][ma][k4a]      = av0;                                 \
        *(float4*)&As[S][ma + 64][k4a] = av1;                                 \
        *(float4*)&Bs[S][kb][n4b]      = bv0;                                 \
        *(float4*)&Bs[S][kb + 8][n4b]  = bv1;                                 \
    } while (0)

    PLOAD(0);
    PSTORE(0);
    __syncthreads();

    for (int c = 0; c < 32; c++) {
        const int s = c & 1;
        if (c + 1 < 32) PLOAD((c + 1) * 16);
#pragma unroll
        for (int kk = 0; kk < 16; kk += 8) {
            uint32_t a[4][4], b[4][2];
#pragma unroll
            for (int mt = 0; mt < 4; mt++) {
                const int row = mw * 64 + mt * 16 + gid;
                a[mt][0] = cvt_tf32(As[s][row][kk + tig]);
                a[mt][1] = cvt_tf32(As[s][row + 8][kk + tig]);
                a[mt][2] = cvt_tf32(As[s][row][kk + tig + 4]);
                a[mt][3] = cvt_tf32(As[s][row + 8][kk + tig + 4]);
            }
#pragma unroll
            for (int nt = 0; nt < 4; nt++) {
                const int col = nw * 32 + nt * 8 + gid;
                b[nt][0] = cvt_tf32(Bs[s][kk + tig][col]);
                b[nt][1] = cvt_tf32(Bs[s][kk + tig + 4][col]);
            }
#pragma unroll
            for (int mt = 0; mt < 4; mt++)
#pragma unroll
                for (int nt = 0; nt < 4; nt++)
                    MMA_TF32(acc[mt][nt], a[mt][0], a[mt][1], a[mt][2],
                             a[mt][3], b[nt][0], b[nt][1]);
        }
        if (c + 1 < 32) {
            PSTORE((c + 1) & 1);
            __syncthreads();
        }
    }

    if (!isK) {
#pragma unroll
        for (int mt = 0; mt < 4; mt++) {
#pragma unroll
            for (int nt = 0; nt < 4; nt++) {
                const int row = m0 + mw * 64 + mt * 16 + gid;
                const int col = n0 + nw * 32 + nt * 8 + 2 * tig;
                float2 lo = make_float2(acc[mt][nt][0], acc[mt][nt][1]);
                float2 hi = make_float2(acc[mt][nt][2], acc[mt][nt][3]);
                *(float2*)&g_Q[(size_t)row * Un + col]       = lo;
                *(float2*)&g_Q[(size_t)(row + 8) * Un + col] = hi;
            }
        }
    } else {
        const int bidx = m0 >> 8;
        const int qi0  = m0 & 255;
#pragma unroll
        for (int pass = 0; pass < 2; pass++) {
            __syncthreads();
            if ((nw >> 1) == pass) {
#pragma unroll
                for (int mt = 0; mt < 4; mt++) {
#pragma unroll
                    for (int nt = 0; nt < 4; nt++) {
                        const int row = mw * 64 + mt * 16 + gid;
                        const int cl  = (nw & 1) * 32 + nt * 8 + 2 * tig;
                        kbuf[row][cl]         = acc[mt][nt][0];
                        kbuf[row][cl + 1]     = acc[mt][nt][1];
                        kbuf[row + 8][cl]     = acc[mt][nt][2];
                        kbuf[row + 8][cl + 1] = acc[mt][nt][3];
                    }
                }
            }
            __syncthreads();
#pragma unroll
            for (int i = tid; i < 64 * 128; i += 256) {
                const int ul = i >> 7;
                const int q  = i & 127;
                const int u  = n0 + pass * 64 + ul;
                g_KT[((size_t)bidx * Un + u) * Ln + qi0 + q] =
                    kbuf[q][ul] + __ldg(&bh[u]);
            }
        }
    }
#undef PLOAD
#undef PSTORE
}

// ---------------------------------------------------------------------------
// Kernel 2: fused attention (scores + normalize + output GEMM).
// 256 CTAs x 512 threads (16 warps -> ~28 warps/SM for MUFU latency cover).
// e-loop: thread = (pg 0..7 -> 1 p-row, qg 0..63 -> 4 q), full u=512
// in-thread. 4 tanh/iter behind 1 coalesced LDG.128 + 2 broadcast LDS.
// Then per-warp row normalize, smem transpose, fused epilogue (f = tid).
// ---------------------------------------------------------------------------
#define PT 8

__global__ __launch_bounds__(512) void attn_kernel(
    const float* __restrict__ X,    // [8,256,512]
    const float* __restrict__ Wv,   // [512]
    float* __restrict__ out)        // [8,256,512]
{
    __shared__ float QsT[Un][PT];   // [u][p]  16 KB
    __shared__ float Wvs[Un];       //          2 KB
    __shared__ float aP[PT][Ln];    // [p][q]   8 KB
    __shared__ float aQ[Ln][PT];    // [q][p]   8 KB   (34 KB total)

    const int tid = threadIdx.x;
    const int b  = blockIdx.x >> 5;
    const int p0 = (blockIdx.x & 31) * PT;

    // Stage Q transposed and Wv
#pragma unroll
    for (int i = tid; i < PT * Un; i += 512) {
        int p = i >> 9;          // 0..7
        int u = i & 511;
        QsT[u][p] = g_Q[((size_t)b * Ln + p0 + p) * Un + u];
    }
    Wvs[tid] = Wv[tid];
    __syncthreads();

    // ---- e-loop: 4 tanh / iter / thread ----
    const int pg = tid >> 6;       // 0..7 -> one p row (warp-uniform)
    const int qg = tid & 63;       // 4-wide q group
    const float4* __restrict__ kt4 = (const float4*)(g_KT + (size_t)b * Un * Ln);

    float4 e = make_float4(0.f, 0.f, 0.f, 0.f);
#pragma unroll 4
    for (int u = 0; u < Un; u++) {
        float4 kv = __ldg(&kt4[u * 64 + qg]);
        float  qp = QsT[u][pg];    // warp-uniform broadcast
        float  wv = Wvs[u];
        e.x = fmaf(wv, tanh_approx(qp + kv.x), e.x);
        e.y = fmaf(wv, tanh_approx(qp + kv.y), e.y);
        e.z = fmaf(wv, tanh_approx(qp + kv.z), e.z);
        e.w = fmaf(wv, tanh_approx(qp + kv.w), e.w);
    }
    // ba is a uniform shift of e -> cancels exactly in the exp-normalize.

    *(float4*)&aP[pg][qg * 4] = e;
    __syncthreads();

    // ---- normalize: warp w (< 8) handles row p = w ----
    {
        const int w = tid >> 5, l = tid & 31;
        if (w < PT) {
            float v[8];
            float m = -1e30f;
#pragma unroll
            for (int j = 0; j < 8; j++) {
                v[j] = aP[w][l + j * 32];
                m = fmaxf(m, v[j]);
            }
#pragma unroll
            for (int o = 16; o > 0; o >>= 1)
                m = fmaxf(m, __shfl_xor_sync(0xffffffffu, m, o));
            float s = 0.f;
#pragma unroll
            for (int j = 0; j < 8; j++) {
                v[j] = __expf(v[j] - m);
                s += v[j];
            }
#pragma unroll
            for (int o = 16; o > 0; o >>= 1)
                s += __shfl_xor_sync(0xffffffffu, s, o);
            float inv = 1.f / (s + 1e-7f);
#pragma unroll
            for (int j = 0; j < 8; j++) aP[w][l + j * 32] = v[j] * inv;
        }
    }
    __syncthreads();

    // ---- transpose aP[p][q] -> aQ[q][p] ----
#pragma unroll
    for (int i = tid; i < PT * Ln; i += 512) {
        int p = i >> 8;
        int q = i & 255;
        aQ[q][p] = aP[p][q];
    }
    __syncthreads();

    // ---- fused epilogue: out[p,f] = sum_q a[p][q] * X[b,q,f]; f = tid ----
    float o[PT];
#pragma unroll
    for (int p = 0; p < PT; p++) o[p] = 0.f;

    const float* __restrict__ xin = X + (size_t)b * Ln * Fn;
#pragma unroll 2
    for (int q = 0; q < Ln; q++) {
        float x = __ldg(&xin[q * Fn + tid]);
        float4 aa = *(const float4*)&aQ[q][0];   // warp-uniform broadcast
        float4 ab = *(const float4*)&aQ[q][4];
        o[0] = fmaf(aa.x, x, o[0]);
        o[1] = fmaf(aa.y, x, o[1]);
        o[2] = fmaf(aa.z, x, o[2]);
        o[3] = fmaf(aa.w, x, o[3]);
        o[4] = fmaf(ab.x, x, o[4]);
        o[5] = fmaf(ab.y, x, o[5]);
        o[6] = fmaf(ab.z, x, o[6]);
        o[7] = fmaf(ab.w, x, o[7]);
    }
#pragma unroll
    for (int p = 0; p < PT; p++)
        out[((size_t)b * Ln + p0 + p) * Fn + tid] = o[p];
}

extern "C" void kernel_launch(void* const* d_in, const int* in_sizes, int n_in,
                              void* d_out, int out_size) {
    const float* X  = (const float*)d_in[0];
    const float* Wq = (const float*)d_in[1];
    const float* Wk = (const float*)d_in[2];
    const float* Wv = (const float*)d_in[3];
    const float* bh = (const float*)d_in[4];
    // d_in[5] = ba: cancels exactly in the exp-normalize; unused.
    float* out = (float*)d_out;

    proj_tc_kernel<<<128, 256>>>(X, Wq, Wk, bh);       // 128 CTAs

    attn_kernel<<<Bn * (Ln / PT), 512>>>(X, Wv, out);  // 256 CTAs x 512 thr
}

// round 12
// speedup vs baseline: 1.3845x; 1.0913x over previous
#include <cuda_runtime.h>
#include <cstdint>

// Shapes (fixed): B=8, L=256, F=512, U=512.
#define Bn 8
#define Ln 256
#define Fn 512
#define Un 512
#define Mn (Bn*Ln)   // 2048

// Scratch
__device__ __align__(16) float g_Q[Mn * Un];        // [2048][512]
__device__ __align__(16) float g_KT[Bn * Un * Ln];  // [8][512][256]  K+bh, u-major

__device__ __forceinline__ float tanh_approx(float x) {
    float y;
    asm("tanh.approx.f32 %0, %1;" : "=f"(y) : "f"(x));
    return y;
}

__device__ __forceinline__ uint32_t cvt_tf32(float x) {
    uint32_t r;
    asm("cvt.rna.tf32.f32 %0, %1;" : "=r"(r) : "f"(x));
    return r;
}

#define MMA_TF32(c, A0, A1, A2, A3, B0, B1)                                   \
    asm volatile(                                                             \
        "mma.sync.aligned.m16n8k8.row.col.f32.tf32.tf32.f32 "                 \
        "{%0,%1,%2,%3}, {%4,%5,%6,%7}, {%8,%9}, {%0,%1,%2,%3};"               \
        : "+f"((c)[0]), "+f"((c)[1]), "+f"((c)[2]), "+f"((c)[3])              \
        : "r"(A0), "r"(A1), "r"(A2), "r"(A3), "r"(B0), "r"(B1))

// ---------------------------------------------------------------------------
// Kernel 1: tensor-core projections, smem-staged (validated, ~20us).
// ---------------------------------------------------------------------------
#define APITCH 20
#define BPITCH 136
#define A_FLOATS (2 * 128 * APITCH)
#define B_FLOATS (2 * 16 * BPITCH)

__global__ __launch_bounds__(256) void proj_tc_kernel(
    const float* __restrict__ X,    // [2048,512]
    const float* __restrict__ Wq,   // [512,512]
    const float* __restrict__ Wk,   // [512,512]
    const float* __restrict__ bh)   // [512]
{
    __shared__ __align__(16) float pool[A_FLOATS + B_FLOATS];
    typedef float ATile[128][APITCH];
    typedef float BTile[16][BPITCH];
    ATile* As = (ATile*)pool;
    BTile* Bs = (BTile*)(pool + A_FLOATS);
    typedef float KRow[65];
    KRow* kbuf = (KRow*)pool;   // epilogue alias

    const int bx  = blockIdx.x;
    const int isK = bx >> 6;
    const int m0  = ((bx >> 2) & 15) * 128;
    const int n0  = (bx & 3) * 128;
    const float* __restrict__ W = isK ? Wk : Wq;

    const int tid  = threadIdx.x;
    const int wid  = tid >> 5;
    const int lane = tid & 31;
    const int mw = wid >> 2;
    const int nw = wid & 3;
    const int gid = lane >> 2;
    const int tig = lane & 3;

    const int ma  = tid >> 2;
    const int k4a = (tid & 3) * 4;
    const int kb  = tid >> 5;
    const int n4b = (tid & 31) * 4;

    float acc[4][4][4];
#pragma unroll
    for (int i = 0; i < 4; i++)
#pragma unroll
        for (int j = 0; j < 4; j++)
#pragma unroll
            for (int r = 0; r < 4; r++) acc[i][j][r] = 0.f;

    float4 av0, av1, bv0, bv1;
#define PLOAD(K0)                                                             \
    do {                                                                      \
        av0 = *(const float4*)&X[(size_t)(m0 + ma) * Fn + (K0) + k4a];        \
        av1 = *(const float4*)&X[(size_t)(m0 + ma + 64) * Fn + (K0) + k4a];   \
        bv0 = *(const float4*)&W[(size_t)((K0) + kb) * Un + n0 + n4b];        \
        bv1 = *(const float4*)&W[(size_t)((K0) + kb + 8) * Un + n0 + n4b];    \
    } while (0)
#define PSTORE(S)                                                             \
    do {                                                                      \
        *(float4*)&As[S][ma][k4a]      = av0;                                 \
        *(float4*)&As[S][ma + 64][k4a] = av1;                                 \
        *(float4*)&Bs[S][kb][n4b]      = bv0;                                 \
        *(float4*)&Bs[S][kb + 8][n4b]  = bv1;                                 \
    } while (0)

    PLOAD(0);
    PSTORE(0);
    __syncthreads();

    for (int c = 0; c < 32; c++) {
        const int s = c & 1;
        if (c + 1 < 32) PLOAD((c + 1) * 16);
#pragma unroll
        for (int kk = 0; kk < 16; kk += 8) {
            uint32_t a[4][4], b[4][2];
#pragma unroll
            for (int mt = 0; mt < 4; mt++) {
                const int row = mw * 64 + mt * 16 + gid;
                a[mt][0] = cvt_tf32(As[s][row][kk + tig]);
                a[mt][1] = cvt_tf32(As[s][row + 8][kk + tig]);
                a[mt][2] = cvt_tf32(As[s][row][kk + tig + 4]);
                a[mt][3] = cvt_tf32(As[s][row + 8][kk + tig + 4]);
            }
#pragma unroll
            for (int nt = 0; nt < 4; nt++) {
                const int col = nw * 32 + nt * 8 + gid;
                b[nt][0] = cvt_tf32(Bs[s][kk + tig][col]);
                b[nt][1] = cvt_tf32(Bs[s][kk + tig + 4][col]);
            }
#pragma unroll
            for (int mt = 0; mt < 4; mt++)
#pragma unroll
                for (int nt = 0; nt < 4; nt++)
                    MMA_TF32(acc[mt][nt], a[mt][0], a[mt][1], a[mt][2],
                             a[mt][3], b[nt][0], b[nt][1]);
        }
        if (c + 1 < 32) {
            PSTORE((c + 1) & 1);
            __syncthreads();
        }
    }

    if (!isK) {
#pragma unroll
        for (int mt = 0; mt < 4; mt++) {
#pragma unroll
            for (int nt = 0; nt < 4; nt++) {
                const int row = m0 + mw * 64 + mt * 16 + gid;
                const int col = n0 + nw * 32 + nt * 8 + 2 * tig;
                float2 lo = make_float2(acc[mt][nt][0], acc[mt][nt][1]);
                float2 hi = make_float2(acc[mt][nt][2], acc[mt][nt][3]);
                *(float2*)&g_Q[(size_t)row * Un + col]       = lo;
                *(float2*)&g_Q[(size_t)(row + 8) * Un + col] = hi;
            }
        }
    } else {
        const int bidx = m0 >> 8;
        const int qi0  = m0 & 255;
#pragma unroll
        for (int pass = 0; pass < 2; pass++) {
            __syncthreads();
            if ((nw >> 1) == pass) {
#pragma unroll
                for (int mt = 0; mt < 4; mt++) {
#pragma unroll
                    for (int nt = 0; nt < 4; nt++) {
                        const int row = mw * 64 + mt * 16 + gid;
                        const int cl  = (nw & 1) * 32 + nt * 8 + 2 * tig;
                        kbuf[row][cl]         = acc[mt][nt][0];
                        kbuf[row][cl + 1]     = acc[mt][nt][1];
                        kbuf[row + 8][cl]     = acc[mt][nt][2];
                        kbuf[row + 8][cl + 1] = acc[mt][nt][3];
                    }
                }
            }
            __syncthreads();
#pragma unroll
            for (int i = tid; i < 64 * 128; i += 256) {
                const int ul = i >> 7;
                const int q  = i & 127;
                const int u  = n0 + pass * 64 + ul;
                g_KT[((size_t)bidx * Un + u) * Ln + qi0 + q] =
                    kbuf[q][ul] + __ldg(&bh[u]);
            }
        }
    }
#undef PLOAD
#undef PSTORE
}

// ---------------------------------------------------------------------------
// Kernel 2: fused attention. 256 CTAs x 512 threads, PT=8 rows per CTA.
// In-warp u-split: lane = us(0..3)*8 + qk(0..7); warp w: wq=w&7 -> 32-q block,
// wp=w>>3 -> 4 p-rows. Each thread: 4p x 4q x u-chunk(128) = 16 tanh/iter
// (the measured-optimal mix). Partials reduced by 2 shfl.xor rounds (no ep
// smem). QsT padded [us][i][p] (stride 1032) and Wvs (stride 129) are
// conflict-free across the 4 in-warp us groups.
// ---------------------------------------------------------------------------
#define PT 8

__global__ __launch_bounds__(512, 2) void attn_kernel(
    const float* __restrict__ X,    // [8,256,512]
    const float* __restrict__ Wv,   // [512]
    float* __restrict__ out)        // [8,256,512]
{
    __shared__ float QsT[4 * 1032];   // [us][i 0..127][p 0..7] (+8 pad/us) 16.1 KB
    __shared__ float Wvs[4 * 129];    // [us][i] (+1 pad/us)                 2 KB
    __shared__ float aP[PT][Ln];      // [p][q]                              8 KB
    __shared__ float aQ[Ln][PT];      // [q][p]                              8 KB

    const int tid  = threadIdx.x;
    const int b    = blockIdx.x >> 5;
    const int p0   = (blockIdx.x & 31) * PT;
    const int lane = tid & 31;
    const int w    = tid >> 5;      // 0..15
    const int wq   = w & 7;         // 32-q block
    const int wp   = w >> 3;        // 0..1 -> p rows wp*4..wp*4+3
    const int us   = lane >> 3;     // 0..3 -> u chunk
    const int qk   = lane & 7;      // float4 index within 32-q block

    // Stage Q (padded-transposed) and Wv
#pragma unroll
    for (int idx = tid; idx < PT * Un; idx += 512) {
        int p = idx >> 9;           // 0..7
        int u = idx & 511;
        QsT[(u >> 7) * 1032 + (u & 127) * 8 + p] =
            g_Q[((size_t)b * Ln + p0 + p) * Un + u];
    }
    if (tid < Un) Wvs[(tid >> 7) * 129 + (tid & 127)] = Wv[tid];
    __syncthreads();

    // ---- e-loop: 16 tanh / iter / thread ----
    const float4* __restrict__ kt4 =
        (const float4*)(g_KT + (size_t)b * Un * Ln) + (size_t)us * 128 * 64
        + wq * 8 + qk;
    const float* __restrict__ qb  = &QsT[us * 1032 + wp * 4];
    const float* __restrict__ wvb = &Wvs[us * 129];

    float4 e0 = make_float4(0.f,0.f,0.f,0.f), e1 = e0, e2 = e0, e3 = e0;
#pragma unroll 4
    for (int i = 0; i < 128; i++) {
        float4 kv = __ldg(&kt4[i * 64]);
        float4 q4 = *(const float4*)&qb[i * 8];
        float  wv = wvb[i];
        e0.x = fmaf(wv, tanh_approx(q4.x + kv.x), e0.x);
        e0.y = fmaf(wv, tanh_approx(q4.x + kv.y), e0.y);
        e0.z = fmaf(wv, tanh_approx(q4.x + kv.z), e0.z);
        e0.w = fmaf(wv, tanh_approx(q4.x + kv.w), e0.w);
        e1.x = fmaf(wv, tanh_approx(q4.y + kv.x), e1.x);
        e1.y = fmaf(wv, tanh_approx(q4.y + kv.y), e1.y);
        e1.z = fmaf(wv, tanh_approx(q4.y + kv.z), e1.z);
        e1.w = fmaf(wv, tanh_approx(q4.y + kv.w), e1.w);
        e2.x = fmaf(wv, tanh_approx(q4.z + kv.x), e2.x);
        e2.y = fmaf(wv, tanh_approx(q4.z + kv.y), e2.y);
        e2.z = fmaf(wv, tanh_approx(q4.z + kv.z), e2.z);
        e2.w = fmaf(wv, tanh_approx(q4.z + kv.w), e2.w);
        e3.x = fmaf(wv, tanh_approx(q4.w + kv.x), e3.x);
        e3.y = fmaf(wv, tanh_approx(q4.w + kv.y), e3.y);
        e3.z = fmaf(wv, tanh_approx(q4.w + kv.z), e3.z);
        e3.w = fmaf(wv, tanh_approx(q4.w + kv.w), e3.w);
    }
    // ba is a uniform shift of e -> cancels exactly in the exp-normalize.

    // In-warp reduce over us (lane bits 3,4)
#pragma unroll
    for (int off = 8; off <= 16; off <<= 1) {
        e0.x += __shfl_xor_sync(0xffffffffu, e0.x, off);
        e0.y += __shfl_xor_sync(0xffffffffu, e0.y, off);
        e0.z += __shfl_xor_sync(0xffffffffu, e0.z, off);
        e0.w += __shfl_xor_sync(0xffffffffu, e0.w, off);
        e1.x += __shfl_xor_sync(0xffffffffu, e1.x, off);
        e1.y += __shfl_xor_sync(0xffffffffu, e1.y, off);
        e1.z += __shfl_xor_sync(0xffffffffu, e1.z, off);
        e1.w += __shfl_xor_sync(0xffffffffu, e1.w, off);
        e2.x += __shfl_xor_sync(0xffffffffu, e2.x, off);
        e2.y += __shfl_xor_sync(0xffffffffu, e2.y, off);
        e2.z += __shfl_xor_sync(0xffffffffu, e2.z, off);
        e2.w += __shfl_xor_sync(0xffffffffu, e2.w, off);
        e3.x += __shfl_xor_sync(0xffffffffu, e3.x, off);
        e3.y += __shfl_xor_sync(0xffffffffu, e3.y, off);
        e3.z += __shfl_xor_sync(0xffffffffu, e3.z, off);
        e3.w += __shfl_xor_sync(0xffffffffu, e3.w, off);
    }
    if (us == 0) {
        const int qbase = wq * 32 + qk * 4;
        *(float4*)&aP[wp * 4 + 0][qbase] = e0;
        *(float4*)&aP[wp * 4 + 1][qbase] = e1;
        *(float4*)&aP[wp * 4 + 2][qbase] = e2;
        *(float4*)&aP[wp * 4 + 3][qbase] = e3;
    }
    __syncthreads();

    // ---- normalize: warp ww (< 8) handles row p = ww ----
    {
        const int ww = tid >> 5, l = tid & 31;
        if (ww < PT) {
            float v[8];
            float m = -1e30f;
#pragma unroll
            for (int j = 0; j < 8; j++) {
                v[j] = aP[ww][l + j * 32];
                m = fmaxf(m, v[j]);
            }
#pragma unroll
            for (int o = 16; o > 0; o >>= 1)
                m = fmaxf(m, __shfl_xor_sync(0xffffffffu, m, o));
            float s = 0.f;
#pragma unroll
            for (int j = 0; j < 8; j++) {
                v[j] = __expf(v[j] - m);
                s += v[j];
            }
#pragma unroll
            for (int o = 16; o > 0; o >>= 1)
                s += __shfl_xor_sync(0xffffffffu, s, o);
            float inv = 1.f / (s + 1e-7f);
#pragma unroll
            for (int j = 0; j < 8; j++) aP[ww][l + j * 32] = v[j] * inv;
        }
    }
    __syncthreads();

    // ---- transpose aP[p][q] -> aQ[q][p] ----
#pragma unroll
    for (int i = tid; i < PT * Ln; i += 512) {
        int p = i >> 8;
        int q = i & 255;
        aQ[q][p] = aP[p][q];
    }
    __syncthreads();

    // ---- fused epilogue: out[p,f] = sum_q a[p][q] * X[b,q,f]; f = tid ----
    float o[PT];
#pragma unroll
    for (int p = 0; p < PT; p++) o[p] = 0.f;

    const float* __restrict__ xin = X + (size_t)b * Ln * Fn;
#pragma unroll 2
    for (int q = 0; q < Ln; q++) {
        float x = __ldg(&xin[q * Fn + tid]);
        float4 aa = *(const float4*)&aQ[q][0];
        float4 ab = *(const float4*)&aQ[q][4];
        o[0] = fmaf(aa.x, x, o[0]);
        o[1] = fmaf(aa.y, x, o[1]);
        o[2] = fmaf(aa.z, x, o[2]);
        o[3] = fmaf(aa.w, x, o[3]);
        o[4] = fmaf(ab.x, x, o[4]);
        o[5] = fmaf(ab.y, x, o[5]);
        o[6] = fmaf(ab.z, x, o[6]);
        o[7] = fmaf(ab.w, x, o[7]);
    }
#pragma unroll
    for (int p = 0; p < PT; p++)
        out[((size_t)b * Ln + p0 + p) * Fn + tid] = o[p];
}

extern "C" void kernel_launch(void* const* d_in, const int* in_sizes, int n_in,
                              void* d_out, int out_size) {
    const float* X  = (const float*)d_in[0];
    const float* Wq = (const float*)d_in[1];
    const float* Wk = (const float*)d_in[2];
    const float* Wv = (const float*)d_in[3];
    const float* bh = (const float*)d_in[4];
    // d_in[5] = ba: cancels exactly in the exp-normalize; unused.
    float* out = (float*)d_out;

    proj_tc_kernel<<<128, 256>>>(X, Wq, Wk, bh);       // 128 CTAs

    attn_kernel<<<Bn * (Ln / PT), 512>>>(X, Wv, out);  // 256 CTAs x 512 thr
}